// round 11
// baseline (speedup 1.0000x reference)
#include <cuda_runtime.h>
#include <cuda_fp16.h>
#include <math.h>
#include <stdint.h>

// Problem constants
#define NN   10000
#define EE   80000
#define SD   18
#define HID  1024
#define K2   2048          // fp16 2-term split: A=[hi|lo], W=[whi|whi]
#define LAYERS 4

// GEMM tiling: BM=BN=128, BK=64, 128 threads (4 warps, 2x2 grid of 64x64 warp tiles)
#define BM 128
#define BN 128
#define BK 64
#define STG 3
#define NK (K2 / BK)               // 32
#define TILE_BYTES (128 * 128)     // 16384
#define STAGE_BYTES (2 * TILE_BYTES)
#define MM_SMEM (STG * STAGE_BYTES)   // 98304

// ---------------------------------------------------------------------------
// Scratch (device globals — no runtime allocation allowed)
// ---------------------------------------------------------------------------
__device__ float g_h  [NN * HID];
__device__ float g_HAB[NN * 2048];
__device__ float g_t  [NN * 256];
__device__ __half g_Abig[NN * K2];
__device__ __half g_Rbig[NN * K2];
__device__ __half g_WtAB[LAYERS * 2048 * K2];
__device__ __half g_WtW2[LAYERS * HID * K2];
__device__ __half g_WtG [256 * K2];
__device__ int   g_deg[NN];
__device__ int   g_off[NN + 1];
__device__ int   g_cur[NN];
__device__ int   g_srcs[EE];

// ---------------------------------------------------------------------------
// PTX helpers (baseline ISA only: cp.async / ldmatrix / mma.sync)
// ---------------------------------------------------------------------------
__device__ __forceinline__ uint32_t smem_u32(const void* p) {
    uint32_t a;
    asm("{ .reg .u64 t; cvta.to.shared.u64 t, %1; cvt.u32.u64 %0, t; }" : "=r"(a) : "l"(p));
    return a;
}
__device__ __forceinline__ void cp16(uint32_t dst, const void* src, bool valid) {
    int sz = valid ? 16 : 0;
    asm volatile("cp.async.cg.shared.global [%0], [%1], 16, %2;" :: "r"(dst), "l"(src), "r"(sz) : "memory");
}
__device__ __forceinline__ void cp_commit() { asm volatile("cp.async.commit_group;" ::: "memory"); }
__device__ __forceinline__ void ldm_x4(uint32_t& r0, uint32_t& r1, uint32_t& r2, uint32_t& r3,
                                       uint32_t addr) {
    asm volatile("ldmatrix.sync.aligned.m8n8.x4.shared.b16 {%0,%1,%2,%3}, [%4];"
                 : "=r"(r0), "=r"(r1), "=r"(r2), "=r"(r3) : "r"(addr));
}
__device__ __forceinline__ void mma_fp16(float& c0, float& c1, float& c2, float& c3,
                                         uint32_t a0, uint32_t a1, uint32_t a2, uint32_t a3,
                                         uint32_t b0, uint32_t b1) {
    asm volatile(
        "mma.sync.aligned.m16n8k16.row.col.f32.f16.f16.f32 "
        "{%0,%1,%2,%3}, {%4,%5,%6,%7}, {%8,%9}, {%0,%1,%2,%3};"
        : "+f"(c0), "+f"(c1), "+f"(c2), "+f"(c3)
        : "r"(a0), "r"(a1), "r"(a2), "r"(a3), "r"(b0), "r"(b1));
}

// ---------------------------------------------------------------------------
// HMMA GEMM: C[M, Nstride] = A[M, K2] @ Bt[N, K2]^T  (fp16 in, fp32 out)
// MODE 0: plain C
// MODE 1: v = relu(acc + deg[row]*bias[col]); writes C (fp32) AND abig split
// MODE 2: relu(acc + bias[col]) -> C
// MODE 3: v = relu(acc + deg[row]*bias[col]); writes abig split ONLY
// 128 threads, 4 warps in 2(M) x 2(N); warp tile 64x64; frag m16n8k16.
// Smem: dense 128B rows, 16B-chunk XOR swizzle; conflict-free stores+ldmatrix.
// Mainloop: fragment double-buffering — kk+1 LDSMs issue before kk's MMAs.
// ---------------------------------------------------------------------------
template <int MODE>
__global__ void __launch_bounds__(128, 2)
mma_gemm(const __half* __restrict__ A, const __half* __restrict__ Bt,
         float* __restrict__ C, int M, int Nstride,
         const float* __restrict__ bias, const int* __restrict__ deg,
         __half* __restrict__ abig) {
    extern __shared__ char smem[];
    const uint32_t sb = smem_u32(smem);
    const int tid  = threadIdx.x;
    const int wid  = tid >> 5;
    const int lane = tid & 31;
    const int bm   = blockIdx.y * BM;
    const int bn   = blockIdx.x * BN;
    const int warp_m = (wid & 1) * 64;
    const int warp_n = (wid >> 1) * 64;

    const char* gA = (const char*)A  + (size_t)bm * (K2 * 2);
    const char* gB = (const char*)Bt + (size_t)bn * (K2 * 2);
    const int lrow = tid >> 3;
    const int qq   = (tid & 7) * 16;

    auto load_chunk = [&](int kc, int s) {
        uint32_t sa = sb + s * STAGE_BYTES;
        uint32_t sB = sa + TILE_BYTES;
        size_t kb = (size_t)kc * (BK * 2);
#pragma unroll
        for (int u = 0; u < 8; u++) {
            int row = lrow + u * 16;
            uint32_t sw = row * 128 + (qq ^ ((row & 7) << 4));
            cp16(sa + sw, gA + (size_t)row * (K2 * 2) + kb + qq, (bm + row) < M);
            cp16(sB + sw, gB + (size_t)row * (K2 * 2) + kb + qq, true);
        }
        cp_commit();
    };

    // ldmatrix lane patterns
    const int g  = lane >> 3;
    const int lr = lane & 7;
    const int swz = lr << 4;
    const int A_row = (g & 1) * 8 + lr;
    const int A_col = (g >> 1) * 16;
    const int B_row = (g >> 1) * 8 + lr;
    const int B_col = (g & 1) * 16;

    float acc[4][8][4];
#pragma unroll
    for (int i = 0; i < 4; i++)
#pragma unroll
        for (int j = 0; j < 8; j++)
#pragma unroll
            for (int q = 0; q < 4; q++) acc[i][j][q] = 0.f;

    // prologue
#pragma unroll
    for (int s = 0; s < STG - 1; s++) load_chunk(s, s);

    uint32_t a[2][4][4], b[2][4][4];
    for (int it = 0; it < NK; it++) {
        asm volatile("cp.async.wait_group %0;" :: "n"(STG - 2) : "memory");
        __syncthreads();
        int cl = it + STG - 1;
        if (cl < NK) load_chunk(cl, cl % STG);
        else         cp_commit();      // empty group keeps wait_group bookkeeping valid

        uint32_t sa = sb + (it % STG) * STAGE_BYTES;
        uint32_t sB = sa + TILE_BYTES;
        uint32_t aBase = sa + (warp_m + A_row) * 128;
        uint32_t bBase = sB + (warp_n + B_row) * 128;

        // preload kk=0 fragments
        {
            uint32_t aoff = (uint32_t)((0 * 32 + A_col) ^ swz);
            uint32_t boff = (uint32_t)((0 * 32 + B_col) ^ swz);
#pragma unroll
            for (int mt = 0; mt < 4; mt++)
                ldm_x4(a[0][mt][0], a[0][mt][1], a[0][mt][2], a[0][mt][3],
                       aBase + mt * (16 * 128) + aoff);
#pragma unroll
            for (int nt2 = 0; nt2 < 4; nt2++)
                ldm_x4(b[0][nt2][0], b[0][nt2][1], b[0][nt2][2], b[0][nt2][3],
                       bBase + nt2 * (16 * 128) + boff);
        }
#pragma unroll
        for (int kk = 0; kk < 4; kk++) {
            const int cur = kk & 1;
            const int nxt = cur ^ 1;
            if (kk < 3) {   // issue next step's LDSMs before this step's MMAs
                uint32_t aoff = (uint32_t)(((kk + 1) * 32 + A_col) ^ swz);
                uint32_t boff = (uint32_t)(((kk + 1) * 32 + B_col) ^ swz);
#pragma unroll
                for (int mt = 0; mt < 4; mt++)
                    ldm_x4(a[nxt][mt][0], a[nxt][mt][1], a[nxt][mt][2], a[nxt][mt][3],
                           aBase + mt * (16 * 128) + aoff);
#pragma unroll
                for (int nt2 = 0; nt2 < 4; nt2++)
                    ldm_x4(b[nxt][nt2][0], b[nxt][nt2][1], b[nxt][nt2][2], b[nxt][nt2][3],
                           bBase + nt2 * (16 * 128) + boff);
            }
#pragma unroll
            for (int mt = 0; mt < 4; mt++)
#pragma unroll
                for (int nt = 0; nt < 8; nt++) {
                    uint32_t bb0 = b[cur][nt >> 1][(nt & 1) * 2 + 0];
                    uint32_t bb1 = b[cur][nt >> 1][(nt & 1) * 2 + 1];
                    mma_fp16(acc[mt][nt][0], acc[mt][nt][1], acc[mt][nt][2], acc[mt][nt][3],
                             a[cur][mt][0], a[cur][mt][1], a[cur][mt][2], a[cur][mt][3],
                             bb0, bb1);
                }
        }
    }

    // epilogue (register-only inputs; no smem reads, no barrier needed)
    const int tq = lane >> 2;      // 0..7
    const int tr = lane & 3;       // 0..3
#pragma unroll
    for (int mt = 0; mt < 4; mt++) {
#pragma unroll
        for (int half = 0; half < 2; half++) {
            int row = bm + warp_m + mt * 16 + half * 8 + tq;
            if (row >= M) continue;
            float degf = 0.f;
            if (MODE == 1 || MODE == 3) degf = (float)deg[row];
#pragma unroll
            for (int nt = 0; nt < 8; nt++) {
                int col = bn + warp_n + nt * 8 + tr * 2;
                float vx = acc[mt][nt][half * 2 + 0];
                float vy = acc[mt][nt][half * 2 + 1];
                if (MODE == 1 || MODE == 3) {
                    vx = fmaxf(fmaf(degf, bias[col + 0], vx), 0.f);
                    vy = fmaxf(fmaf(degf, bias[col + 1], vy), 0.f);
                } else if (MODE == 2) {
                    vx = fmaxf(vx + bias[col + 0], 0.f);
                    vy = fmaxf(vy + bias[col + 1], 0.f);
                }
                if (MODE != 3)
                    *reinterpret_cast<float2*>(&C[(size_t)row * Nstride + col]) = make_float2(vx, vy);
                if (MODE == 1 || MODE == 3) {
                    __half hx = __float2half(vx);
                    __half hy = __float2half(vy);
                    __half lx = __float2half(vx - __half2float(hx));
                    __half ly = __float2half(vy - __half2float(hy));
                    size_t base = (size_t)row * K2 + col;
                    *reinterpret_cast<__half2*>(&abig[base])       = __halves2half2(hx, hy);
                    *reinterpret_cast<__half2*>(&abig[base + HID]) = __halves2half2(lx, ly);
                }
            }
        }
    }
}

// ---------------------------------------------------------------------------
// All weight conversions in ONE launch. blockIdx.z selects the slice:
//   s = 3*l + 0: WtAB rows 0..1023   = (W1a - W1b)^T      (layer l)
//   s = 3*l + 1: WtAB rows 1024..2047 = W1b^T             (layer l)
//   s = 3*l + 2: WtW2 (layer l) = W2^T
//   s = 12     : WtG = gw1^T   (N=256)
// out[n][0:K]=whi, [K:2K]=whi (fp16, transposed)
// ---------------------------------------------------------------------------
__global__ void convW_all(const float* __restrict__ W1, const float* __restrict__ W2,
                          const float* __restrict__ gw1,
                          __half* __restrict__ WtAB, __half* __restrict__ WtW2,
                          __half* __restrict__ WtG) {
    const size_t KK = (size_t)HID * HID;
    int s = blockIdx.z;
    const float* Wa;
    const float* Wb = nullptr;
    __half* out;
    int N = HID;
    if (s < 12) {
        int l = s / 3, k = s - l * 3;
        if (k == 0)      { Wa = W1 + (size_t)l * 2 * KK; Wb = Wa + KK; out = WtAB + (size_t)l * 2048 * K2; }
        else if (k == 1) { Wa = W1 + (size_t)l * 2 * KK + KK;          out = WtAB + (size_t)l * 2048 * K2 + (size_t)1024 * K2; }
        else             { Wa = W2 + (size_t)l * KK;                   out = WtW2 + (size_t)l * HID * K2; }
    } else { Wa = gw1; out = WtG; N = 256; }

    int n0 = blockIdx.x * 32, k0 = blockIdx.y * 32;
    if (n0 >= N) return;
    __shared__ float t[32][33];
    int tx = threadIdx.x, ty = threadIdx.y;
#pragma unroll
    for (int r = ty; r < 32; r += 8) {
        float v = Wa[(size_t)(k0 + r) * N + n0 + tx];
        if (Wb) v -= Wb[(size_t)(k0 + r) * N + n0 + tx];
        t[r][tx] = v;
    }
    __syncthreads();
#pragma unroll
    for (int r = ty; r < 32; r += 8) {
        int n = n0 + r, k = k0 + tx;
        __half hi = __float2half(t[tx][r]);
        size_t base = (size_t)n * K2;
        out[base + k] = hi;
        out[base + HID + k] = hi;
    }
}

// ---------------------------------------------------------------------------
// CSR build (deterministic)
// ---------------------------------------------------------------------------
__global__ void zero_int_kernel(int* p, int n) {
    int i = blockIdx.x * blockDim.x + threadIdx.x;
    if (i < n) p[i] = 0;
}
__global__ void hist_kernel(const int* __restrict__ dst, int* __restrict__ deg) {
    int e = blockIdx.x * blockDim.x + threadIdx.x;
    if (e < EE) atomicAdd(&deg[dst[e]], 1);
}
// single-block scan: 10 nodes per thread, one Hillis-Steele over 1024 partials
__global__ void scan_kernel(const int* __restrict__ deg, int* __restrict__ off) {
    __shared__ int sh[1024];
    int t = threadIdx.x;
    int base = t * 10;
    int v[10];
    int s = 0;
#pragma unroll
    for (int u = 0; u < 10; u++) {
        int i = base + u;
        v[u] = (i < NN) ? deg[i] : 0;
        s += v[u];
    }
    sh[t] = s;
    __syncthreads();
#pragma unroll
    for (int d = 1; d < 1024; d <<= 1) {
        int x = (t >= d) ? sh[t - d] : 0;
        __syncthreads();
        sh[t] += x;
        __syncthreads();
    }
    int run = (t == 0) ? 0 : sh[t - 1];
#pragma unroll
    for (int u = 0; u < 10; u++) {
        int i = base + u;
        run += v[u];
        if (i < NN) off[i + 1] = run;
    }
    if (t == 0) off[0] = 0;
}
__global__ void copy_off_kernel(const int* __restrict__ off, int* __restrict__ cur) {
    int i = blockIdx.x * blockDim.x + threadIdx.x;
    if (i < NN) cur[i] = off[i];
}
__global__ void scatter_kernel(const int* __restrict__ src, const int* __restrict__ dst,
                               int* __restrict__ cur, int* __restrict__ srcs) {
    int e = blockIdx.x * blockDim.x + threadIdx.x;
    if (e < EE) {
        int p = atomicAdd(&cur[dst[e]], 1);
        srcs[p] = src[e];
    }
}
__global__ void sort_kernel(const int* __restrict__ off, int* __restrict__ srcs) {
    int i = blockIdx.x * blockDim.x + threadIdx.x;
    if (i >= NN) return;
    int a = off[i], b = off[i + 1];
    for (int x = a + 1; x < b; x++) {
        int v = srcs[x];
        int y = x - 1;
        while (y >= a && srcs[y] > v) { srcs[y + 1] = srcs[y]; y--; }
        srcs[y + 1] = v;
    }
}

// ---------------------------------------------------------------------------
// Phase embedding: writes fp16 split Abig directly
// ---------------------------------------------------------------------------
__global__ void proj_kernel(const float* __restrict__ x, const float* __restrict__ pw,
                            __half* __restrict__ Abig) {
    int idx = blockIdx.x * blockDim.x + threadIdx.x;
    if (idx >= NN * HID) return;
    int n = idx >> 10, j = idx & (HID - 1);
    float p = 0.f;
#pragma unroll
    for (int k = 0; k < SD; k++) p = fmaf(x[n * SD + k], pw[k * HID + j], p);
    float v = sinf(p) * cosf(p);
    __half hi = __float2half(v);
    __half lo = __float2half(v - __half2float(hi));
    size_t base = (size_t)n * K2;
    Abig[base + j] = hi;
    Abig[base + HID + j] = lo;
}

// ---------------------------------------------------------------------------
// Edge aggregation: R[i] = sum relu(HA[i] + HB[src] + b1); writes fp16 split
// HAB layout: row n holds [HA(n) | HB(n)] (2048 floats)
// ---------------------------------------------------------------------------
__global__ void edge_agg_kernel(const float* __restrict__ HAB,
                                const int* __restrict__ off, const int* __restrict__ srcs,
                                const float* __restrict__ b1, __half* __restrict__ Rbig) {
    int i   = blockIdx.x;
    int tid = threadIdx.x;
    float ha[4], acc[4];
#pragma unroll
    for (int u = 0; u < 4; u++) {
        int j  = tid + u * 256;
        ha[u]  = HAB[(size_t)i * 2048 + j] + b1[j];
        acc[u] = 0.f;
    }
    int s0 = off[i], s1 = off[i + 1];
    for (int e = s0; e < s1; e++) {
        int s = srcs[e];
        const float* hb = HAB + (size_t)s * 2048 + 1024;
#pragma unroll
        for (int u = 0; u < 4; u++) acc[u] += fmaxf(ha[u] + hb[tid + u * 256], 0.f);
    }
    size_t base = (size_t)i * K2;
#pragma unroll
    for (int u = 0; u < 4; u++) {
        int j = tid + u * 256;
        float v = acc[u];
        __half hi = __float2half(v);
        __half lo = __float2half(v - __half2float(hi));
        Rbig[base + j] = hi;
        Rbig[base + HID + j] = lo;
    }
}

// ---------------------------------------------------------------------------
// Heads
// ---------------------------------------------------------------------------
__global__ void ghost_kernel(const float* __restrict__ t, const float* __restrict__ gw2,
                             const float* __restrict__ gb2, float* __restrict__ out) {
    int warp = (blockIdx.x * blockDim.x + threadIdx.x) >> 5;
    int lane = threadIdx.x & 31;
    if (warp >= NN) return;
    float s = 0.f;
#pragma unroll
    for (int k = lane; k < 256; k += 32) s = fmaf(t[(size_t)warp * 256 + k], gw2[k], s);
#pragma unroll
    for (int o = 16; o; o >>= 1) s += __shfl_xor_sync(0xFFFFFFFFu, s, o);
    if (lane == 0) out[warp] = 1.f / (1.f + expf(-(s + gb2[0])));
}
__global__ void stable_kernel(const float* __restrict__ h, const float* __restrict__ sw,
                              const float* __restrict__ sb, float* __restrict__ out) {
    int n    = blockIdx.x;
    int c    = threadIdx.y;
    int lane = threadIdx.x;
    float s  = 0.f;
    for (int k = lane; k < HID; k += 32) s = fmaf(h[(size_t)n * HID + k], sw[k * SD + c], s);
#pragma unroll
    for (int o = 16; o; o >>= 1) s += __shfl_xor_sync(0xFFFFFFFFu, s, o);
    if (lane == 0) out[(size_t)n * SD + c] = s + sb[c];
}

// ---------------------------------------------------------------------------
// Launch
// ---------------------------------------------------------------------------
extern "C" void kernel_launch(void* const* d_in, const int* in_sizes, int n_in,
                              void* d_out, int out_size) {
    const float* x      = (const float*)d_in[0];
    const int*   eidx   = (const int*)  d_in[1];
    const float* proj_w = (const float*)d_in[2];
    const float* W1     = (const float*)d_in[3];
    const float* b1     = (const float*)d_in[4];
    const float* W2     = (const float*)d_in[5];
    const float* b2     = (const float*)d_in[6];
    const float* gw1    = (const float*)d_in[7];
    const float* gb1    = (const float*)d_in[8];
    const float* gw2    = (const float*)d_in[9];
    const float* gb2    = (const float*)d_in[10];
    const float* sw     = (const float*)d_in[11];
    const float* sb     = (const float*)d_in[12];
    float* out = (float*)d_out;

    const int* e_src = eidx;
    const int* e_dst = eidx + EE;

    float *p_h, *p_HAB, *p_t;
    __half *p_Abig, *p_Rbig, *p_WtAB, *p_WtW2, *p_WtG;
    int *p_deg, *p_off, *p_cur, *p_srcs;
    cudaGetSymbolAddress((void**)&p_h,    g_h);
    cudaGetSymbolAddress((void**)&p_HAB,  g_HAB);
    cudaGetSymbolAddress((void**)&p_t,    g_t);
    cudaGetSymbolAddress((void**)&p_Abig, g_Abig);
    cudaGetSymbolAddress((void**)&p_Rbig, g_Rbig);
    cudaGetSymbolAddress((void**)&p_WtAB, g_WtAB);
    cudaGetSymbolAddress((void**)&p_WtW2, g_WtW2);
    cudaGetSymbolAddress((void**)&p_WtG,  g_WtG);
    cudaGetSymbolAddress((void**)&p_deg,  g_deg);
    cudaGetSymbolAddress((void**)&p_off,  g_off);
    cudaGetSymbolAddress((void**)&p_cur,  g_cur);
    cudaGetSymbolAddress((void**)&p_srcs, g_srcs);

    cudaFuncSetAttribute(mma_gemm<0>, cudaFuncAttributeMaxDynamicSharedMemorySize, MM_SMEM);
    cudaFuncSetAttribute(mma_gemm<1>, cudaFuncAttributeMaxDynamicSharedMemorySize, MM_SMEM);
    cudaFuncSetAttribute(mma_gemm<2>, cudaFuncAttributeMaxDynamicSharedMemorySize, MM_SMEM);
    cudaFuncSetAttribute(mma_gemm<3>, cudaFuncAttributeMaxDynamicSharedMemorySize, MM_SMEM);

    const int NBM = (NN + BM - 1) / BM;      // 79
    dim3 gAB(2048 / BN, NBM);                // (16, 79)
    dim3 gW2(HID / BN, NBM);                 // (8, 79)
    dim3 ghead(256 / BN, NBM);               // (2, 79)
    float* h_last = out + NN + (size_t)NN * SD;   // final h lives in d_out directly

    // All weight conversions, one launch
    convW_all<<<dim3(32, 32, 13), dim3(32, 8)>>>(W1, W2, gw1, p_WtAB, p_WtW2, p_WtG);

    // CSR build
    zero_int_kernel<<<(NN + 255) / 256, 256>>>(p_deg, NN);
    hist_kernel<<<(EE + 255) / 256, 256>>>(e_dst, p_deg);
    scan_kernel<<<1, 1024>>>(p_deg, p_off);
    copy_off_kernel<<<(NN + 255) / 256, 256>>>(p_off, p_cur);
    scatter_kernel<<<(EE + 255) / 256, 256>>>(e_src, e_dst, p_cur, p_srcs);
    sort_kernel<<<(NN + 255) / 256, 256>>>(p_off, p_srcs);

    // Phase embedding -> Abig (fp16 split)
    proj_kernel<<<(NN * HID + 255) / 256, 256>>>(x, proj_w, p_Abig);

    // Layers: layers 0..2 skip the dead fp32 h store (MODE 3)
    for (int l = 0; l < LAYERS; l++) {
        const __half* WtAB = p_WtAB + (size_t)l * 2048 * K2;
        const __half* WtW2 = p_WtW2 + (size_t)l * HID * K2;
        const float* b1l = b1 + (size_t)l * HID;
        const float* b2l = b2 + (size_t)l * HID;

        mma_gemm<0><<<gAB, 128, MM_SMEM>>>(p_Abig, WtAB, p_HAB, NN, 2048, nullptr, nullptr, nullptr);
        edge_agg_kernel<<<NN, 256>>>(p_HAB, p_off, p_srcs, b1l, p_Rbig);
        if (l == LAYERS - 1)
            mma_gemm<1><<<gW2, 128, MM_SMEM>>>(p_Rbig, WtW2, h_last, NN, HID, b2l, p_deg, p_Abig);
        else
            mma_gemm<3><<<gW2, 128, MM_SMEM>>>(p_Rbig, WtW2, p_h, NN, HID, b2l, p_deg, p_Abig);
    }

    // Heads (final h already resides in d_out)
    mma_gemm<2><<<ghead, 128, MM_SMEM>>>(p_Abig, p_WtG, p_t, NN, 256, gb1, nullptr, nullptr);
    ghost_kernel<<<(NN * 32 + 255) / 256, 256>>>(p_t, gw2, gb2, out);
    stable_kernel<<<NN, dim3(32, SD)>>>(h_last, sw, sb, out + NN);
}

// round 12
// speedup vs baseline: 1.5191x; 1.5191x over previous
#include <cuda_runtime.h>
#include <cuda_fp16.h>
#include <math.h>
#include <stdint.h>

// Problem constants
#define NN   10000
#define EE   80000
#define SD   18
#define HID  1024
#define K2   2048          // fp16 2-term split: A=[hi|lo], W=[whi|whi]
#define LAYERS 4

// GEMM tiling: BM=BN=128, BK=64, 128 threads (4 warps, 2x2 grid of 64x64 warp tiles)
#define BM 128
#define BN 128
#define BK 64
#define STG 3
#define NK (K2 / BK)               // 32
#define TILE_BYTES (128 * 128)     // 16384
#define STAGE_BYTES (2 * TILE_BYTES)
#define MM_SMEM (STG * STAGE_BYTES)   // 98304

// ---------------------------------------------------------------------------
// Scratch (device globals — no runtime allocation allowed)
// ---------------------------------------------------------------------------
__device__ float g_h  [NN * HID];
__device__ float g_HAB[NN * 2048];
__device__ float g_t  [NN * 256];
__device__ __half g_Abig[NN * K2];
__device__ __half g_Rbig[NN * K2];
__device__ __half g_WtAB[LAYERS * 2048 * K2];
__device__ __half g_WtW2[LAYERS * HID * K2];
__device__ __half g_WtG [256 * K2];
__device__ int   g_deg[NN];
__device__ int   g_off[NN + 1];
__device__ int   g_cur[NN];
__device__ int   g_srcs[EE];

// ---------------------------------------------------------------------------
// PTX helpers (baseline ISA only: cp.async / ldmatrix / mma.sync)
// ---------------------------------------------------------------------------
__device__ __forceinline__ uint32_t smem_u32(const void* p) {
    uint32_t a;
    asm("{ .reg .u64 t; cvta.to.shared.u64 t, %1; cvt.u32.u64 %0, t; }" : "=r"(a) : "l"(p));
    return a;
}
__device__ __forceinline__ void cp16(uint32_t dst, const void* src, bool valid) {
    int sz = valid ? 16 : 0;
    asm volatile("cp.async.cg.shared.global [%0], [%1], 16, %2;" :: "r"(dst), "l"(src), "r"(sz) : "memory");
}
__device__ __forceinline__ void cp_commit() { asm volatile("cp.async.commit_group;" ::: "memory"); }
__device__ __forceinline__ void ldm_x4(uint32_t& r0, uint32_t& r1, uint32_t& r2, uint32_t& r3,
                                       uint32_t addr) {
    asm volatile("ldmatrix.sync.aligned.m8n8.x4.shared.b16 {%0,%1,%2,%3}, [%4];"
                 : "=r"(r0), "=r"(r1), "=r"(r2), "=r"(r3) : "r"(addr));
}
__device__ __forceinline__ void mma_fp16(float& c0, float& c1, float& c2, float& c3,
                                         uint32_t a0, uint32_t a1, uint32_t a2, uint32_t a3,
                                         uint32_t b0, uint32_t b1) {
    asm volatile(
        "mma.sync.aligned.m16n8k16.row.col.f32.f16.f16.f32 "
        "{%0,%1,%2,%3}, {%4,%5,%6,%7}, {%8,%9}, {%0,%1,%2,%3};"
        : "+f"(c0), "+f"(c1), "+f"(c2), "+f"(c3)
        : "r"(a0), "r"(a1), "r"(a2), "r"(a3), "r"(b0), "r"(b1));
}

// ---------------------------------------------------------------------------
// HMMA GEMM: C[M, Nstride] = A[M, K2] @ Bt[N, K2]^T  (fp16 in, fp32 out)
// MODE 0: plain C
// MODE 1: v = relu(acc + deg[row]*bias[col]); writes C (fp32) AND abig split
// MODE 2: relu(acc + bias[col]) -> C
// MODE 3: v = relu(acc + deg[row]*bias[col]); writes abig split ONLY
// 128 threads, 4 warps in 2(M) x 2(N); warp tile 64x64; frag m16n8k16.
// Single-buffer fragments (R10 layout): at 2 CTAs/SM the warp mix already
// hides LDSM latency; extra fragment buffers spill and regress (R11 lesson).
// ---------------------------------------------------------------------------
template <int MODE>
__global__ void __launch_bounds__(128, 2)
mma_gemm(const __half* __restrict__ A, const __half* __restrict__ Bt,
         float* __restrict__ C, int M, int Nstride,
         const float* __restrict__ bias, const int* __restrict__ deg,
         __half* __restrict__ abig) {
    extern __shared__ char smem[];
    const uint32_t sb = smem_u32(smem);
    const int tid  = threadIdx.x;
    const int wid  = tid >> 5;
    const int lane = tid & 31;
    const int bm   = blockIdx.y * BM;
    const int bn   = blockIdx.x * BN;
    const int warp_m = (wid & 1) * 64;
    const int warp_n = (wid >> 1) * 64;

    const char* gA = (const char*)A  + (size_t)bm * (K2 * 2);
    const char* gB = (const char*)Bt + (size_t)bn * (K2 * 2);
    const int lrow = tid >> 3;
    const int qq   = (tid & 7) * 16;

    auto load_chunk = [&](int kc, int s) {
        uint32_t sa = sb + s * STAGE_BYTES;
        uint32_t sB = sa + TILE_BYTES;
        size_t kb = (size_t)kc * (BK * 2);
#pragma unroll
        for (int u = 0; u < 8; u++) {
            int row = lrow + u * 16;
            uint32_t sw = row * 128 + (qq ^ ((row & 7) << 4));
            cp16(sa + sw, gA + (size_t)row * (K2 * 2) + kb + qq, (bm + row) < M);
            cp16(sB + sw, gB + (size_t)row * (K2 * 2) + kb + qq, true);
        }
        cp_commit();
    };

    // ldmatrix lane patterns
    const int g  = lane >> 3;
    const int lr = lane & 7;
    const int swz = lr << 4;
    const int A_row = (g & 1) * 8 + lr;
    const int A_col = (g >> 1) * 16;
    const int B_row = (g >> 1) * 8 + lr;
    const int B_col = (g & 1) * 16;

    float acc[4][8][4];
#pragma unroll
    for (int i = 0; i < 4; i++)
#pragma unroll
        for (int j = 0; j < 8; j++)
#pragma unroll
            for (int q = 0; q < 4; q++) acc[i][j][q] = 0.f;

    // prologue
#pragma unroll
    for (int s = 0; s < STG - 1; s++) load_chunk(s, s);

    for (int it = 0; it < NK; it++) {
        asm volatile("cp.async.wait_group %0;" :: "n"(STG - 2) : "memory");
        __syncthreads();
        int cl = it + STG - 1;
        if (cl < NK) load_chunk(cl, cl % STG);
        else         cp_commit();      // empty group keeps wait_group bookkeeping valid

        uint32_t sa = sb + (it % STG) * STAGE_BYTES;
        uint32_t sB = sa + TILE_BYTES;
        uint32_t aBase = sa + (warp_m + A_row) * 128;
        uint32_t bBase = sB + (warp_n + B_row) * 128;
#pragma unroll
        for (int kk = 0; kk < 4; kk++) {
            uint32_t a[4][4], b[4][4];
            uint32_t aoff = (uint32_t)((kk * 32 + A_col) ^ swz);
            uint32_t boff = (uint32_t)((kk * 32 + B_col) ^ swz);
#pragma unroll
            for (int mt = 0; mt < 4; mt++)
                ldm_x4(a[mt][0], a[mt][1], a[mt][2], a[mt][3],
                       aBase + mt * (16 * 128) + aoff);
#pragma unroll
            for (int nt2 = 0; nt2 < 4; nt2++)
                ldm_x4(b[nt2][0], b[nt2][1], b[nt2][2], b[nt2][3],
                       bBase + nt2 * (16 * 128) + boff);
#pragma unroll
            for (int mt = 0; mt < 4; mt++)
#pragma unroll
                for (int nt = 0; nt < 8; nt++) {
                    uint32_t bb0 = b[nt >> 1][(nt & 1) * 2 + 0];
                    uint32_t bb1 = b[nt >> 1][(nt & 1) * 2 + 1];
                    mma_fp16(acc[mt][nt][0], acc[mt][nt][1], acc[mt][nt][2], acc[mt][nt][3],
                             a[mt][0], a[mt][1], a[mt][2], a[mt][3], bb0, bb1);
                }
        }
    }

    // epilogue (register-only inputs; no smem reads, no barrier needed)
    const int tq = lane >> 2;      // 0..7
    const int tr = lane & 3;       // 0..3
#pragma unroll
    for (int mt = 0; mt < 4; mt++) {
#pragma unroll
        for (int half = 0; half < 2; half++) {
            int row = bm + warp_m + mt * 16 + half * 8 + tq;
            if (row >= M) continue;
            float degf = 0.f;
            if (MODE == 1 || MODE == 3) degf = (float)deg[row];
#pragma unroll
            for (int nt = 0; nt < 8; nt++) {
                int col = bn + warp_n + nt * 8 + tr * 2;
                float vx = acc[mt][nt][half * 2 + 0];
                float vy = acc[mt][nt][half * 2 + 1];
                if (MODE == 1 || MODE == 3) {
                    vx = fmaxf(fmaf(degf, bias[col + 0], vx), 0.f);
                    vy = fmaxf(fmaf(degf, bias[col + 1], vy), 0.f);
                } else if (MODE == 2) {
                    vx = fmaxf(vx + bias[col + 0], 0.f);
                    vy = fmaxf(vy + bias[col + 1], 0.f);
                }
                if (MODE != 3)
                    *reinterpret_cast<float2*>(&C[(size_t)row * Nstride + col]) = make_float2(vx, vy);
                if (MODE == 1 || MODE == 3) {
                    __half hx = __float2half(vx);
                    __half hy = __float2half(vy);
                    __half lx = __float2half(vx - __half2float(hx));
                    __half ly = __float2half(vy - __half2float(hy));
                    size_t base = (size_t)row * K2 + col;
                    *reinterpret_cast<__half2*>(&abig[base])       = __halves2half2(hx, hy);
                    *reinterpret_cast<__half2*>(&abig[base + HID]) = __halves2half2(lx, ly);
                }
            }
        }
    }
}

// ---------------------------------------------------------------------------
// All weight conversions in ONE launch. blockIdx.z selects the slice:
//   s = 3*l + 0: WtAB rows 0..1023   = (W1a - W1b)^T      (layer l)
//   s = 3*l + 1: WtAB rows 1024..2047 = W1b^T             (layer l)
//   s = 3*l + 2: WtW2 (layer l) = W2^T
//   s = 12     : WtG = gw1^T   (N=256)
// ---------------------------------------------------------------------------
__global__ void convW_all(const float* __restrict__ W1, const float* __restrict__ W2,
                          const float* __restrict__ gw1,
                          __half* __restrict__ WtAB, __half* __restrict__ WtW2,
                          __half* __restrict__ WtG) {
    const size_t KK = (size_t)HID * HID;
    int s = blockIdx.z;
    const float* Wa;
    const float* Wb = nullptr;
    __half* out;
    int N = HID;
    if (s < 12) {
        int l = s / 3, k = s - l * 3;
        if (k == 0)      { Wa = W1 + (size_t)l * 2 * KK; Wb = Wa + KK; out = WtAB + (size_t)l * 2048 * K2; }
        else if (k == 1) { Wa = W1 + (size_t)l * 2 * KK + KK;          out = WtAB + (size_t)l * 2048 * K2 + (size_t)1024 * K2; }
        else             { Wa = W2 + (size_t)l * KK;                   out = WtW2 + (size_t)l * HID * K2; }
    } else { Wa = gw1; out = WtG; N = 256; }

    int n0 = blockIdx.x * 32, k0 = blockIdx.y * 32;
    if (n0 >= N) return;
    __shared__ float t[32][33];
    int tx = threadIdx.x, ty = threadIdx.y;
#pragma unroll
    for (int r = ty; r < 32; r += 8) {
        float v = Wa[(size_t)(k0 + r) * N + n0 + tx];
        if (Wb) v -= Wb[(size_t)(k0 + r) * N + n0 + tx];
        t[r][tx] = v;
    }
    __syncthreads();
#pragma unroll
    for (int r = ty; r < 32; r += 8) {
        int n = n0 + r, k = k0 + tx;
        __half hi = __float2half(t[tx][r]);
        size_t base = (size_t)n * K2;
        out[base + k] = hi;
        out[base + HID + k] = hi;
    }
}

// ---------------------------------------------------------------------------
// CSR build (deterministic)
// ---------------------------------------------------------------------------
__global__ void zero_int_kernel(int* p, int n) {
    int i = blockIdx.x * blockDim.x + threadIdx.x;
    if (i < n) p[i] = 0;
}
__global__ void hist_kernel(const int* __restrict__ dst, int* __restrict__ deg) {
    int e = blockIdx.x * blockDim.x + threadIdx.x;
    if (e < EE) atomicAdd(&deg[dst[e]], 1);
}
// single-block scan: 10 nodes/thread, one Hillis-Steele; also seeds cur[]
__global__ void scan_kernel(const int* __restrict__ deg, int* __restrict__ off,
                            int* __restrict__ cur) {
    __shared__ int sh[1024];
    int t = threadIdx.x;
    int base = t * 10;
    int v[10];
    int s = 0;
#pragma unroll
    for (int u = 0; u < 10; u++) {
        int i = base + u;
        v[u] = (i < NN) ? deg[i] : 0;
        s += v[u];
    }
    sh[t] = s;
    __syncthreads();
#pragma unroll
    for (int d = 1; d < 1024; d <<= 1) {
        int x = (t >= d) ? sh[t - d] : 0;
        __syncthreads();
        sh[t] += x;
        __syncthreads();
    }
    int run = (t == 0) ? 0 : sh[t - 1];
#pragma unroll
    for (int u = 0; u < 10; u++) {
        int i = base + u;
        if (i < NN) cur[i] = run;
        run += v[u];
        if (i < NN) off[i + 1] = run;
    }
    if (t == 0) off[0] = 0;
}
__global__ void scatter_kernel(const int* __restrict__ src, const int* __restrict__ dst,
                               int* __restrict__ cur, int* __restrict__ srcs) {
    int e = blockIdx.x * blockDim.x + threadIdx.x;
    if (e < EE) {
        int p = atomicAdd(&cur[dst[e]], 1);
        srcs[p] = src[e];
    }
}
__global__ void sort_kernel(const int* __restrict__ off, int* __restrict__ srcs) {
    int i = blockIdx.x * blockDim.x + threadIdx.x;
    if (i >= NN) return;
    int a = off[i], b = off[i + 1];
    for (int x = a + 1; x < b; x++) {
        int v = srcs[x];
        int y = x - 1;
        while (y >= a && srcs[y] > v) { srcs[y + 1] = srcs[y]; y--; }
        srcs[y + 1] = v;
    }
}

// ---------------------------------------------------------------------------
// Phase embedding: writes fp16 split Abig directly
// ---------------------------------------------------------------------------
__global__ void proj_kernel(const float* __restrict__ x, const float* __restrict__ pw,
                            __half* __restrict__ Abig) {
    int idx = blockIdx.x * blockDim.x + threadIdx.x;
    if (idx >= NN * HID) return;
    int n = idx >> 10, j = idx & (HID - 1);
    float p = 0.f;
#pragma unroll
    for (int k = 0; k < SD; k++) p = fmaf(x[n * SD + k], pw[k * HID + j], p);
    float v = sinf(p) * cosf(p);
    __half hi = __float2half(v);
    __half lo = __float2half(v - __half2float(hi));
    size_t base = (size_t)n * K2;
    Abig[base + j] = hi;
    Abig[base + HID + j] = lo;
}

// ---------------------------------------------------------------------------
// Edge aggregation: R[i] = sum relu(HA[i] + HB[src] + b1); writes fp16 split
// HAB layout: row n holds [HA(n) | HB(n)] (2048 floats)
// ---------------------------------------------------------------------------
__global__ void edge_agg_kernel(const float* __restrict__ HAB,
                                const int* __restrict__ off, const int* __restrict__ srcs,
                                const float* __restrict__ b1, __half* __restrict__ Rbig) {
    int i   = blockIdx.x;
    int tid = threadIdx.x;
    float ha[4], acc[4];
#pragma unroll
    for (int u = 0; u < 4; u++) {
        int j  = tid + u * 256;
        ha[u]  = HAB[(size_t)i * 2048 + j] + b1[j];
        acc[u] = 0.f;
    }
    int s0 = off[i], s1 = off[i + 1];
    for (int e = s0; e < s1; e++) {
        int s = srcs[e];
        const float* hb = HAB + (size_t)s * 2048 + 1024;
#pragma unroll
        for (int u = 0; u < 4; u++) acc[u] += fmaxf(ha[u] + hb[tid + u * 256], 0.f);
    }
    size_t base = (size_t)i * K2;
#pragma unroll
    for (int u = 0; u < 4; u++) {
        int j = tid + u * 256;
        float v = acc[u];
        __half hi = __float2half(v);
        __half lo = __float2half(v - __half2float(hi));
        Rbig[base + j] = hi;
        Rbig[base + HID + j] = lo;
    }
}

// ---------------------------------------------------------------------------
// Heads
// ---------------------------------------------------------------------------
__global__ void ghost_kernel(const float* __restrict__ t, const float* __restrict__ gw2,
                             const float* __restrict__ gb2, float* __restrict__ out) {
    int warp = (blockIdx.x * blockDim.x + threadIdx.x) >> 5;
    int lane = threadIdx.x & 31;
    if (warp >= NN) return;
    float s = 0.f;
#pragma unroll
    for (int k = lane; k < 256; k += 32) s = fmaf(t[(size_t)warp * 256 + k], gw2[k], s);
#pragma unroll
    for (int o = 16; o; o >>= 1) s += __shfl_xor_sync(0xFFFFFFFFu, s, o);
    if (lane == 0) out[warp] = 1.f / (1.f + expf(-(s + gb2[0])));
}
__global__ void stable_kernel(const float* __restrict__ h, const float* __restrict__ sw,
                              const float* __restrict__ sb, float* __restrict__ out) {
    int n    = blockIdx.x;
    int c    = threadIdx.y;
    int lane = threadIdx.x;
    float s  = 0.f;
    for (int k = lane; k < HID; k += 32) s = fmaf(h[(size_t)n * HID + k], sw[k * SD + c], s);
#pragma unroll
    for (int o = 16; o; o >>= 1) s += __shfl_xor_sync(0xFFFFFFFFu, s, o);
    if (lane == 0) out[(size_t)n * SD + c] = s + sb[c];
}

// ---------------------------------------------------------------------------
// Launch
// ---------------------------------------------------------------------------
extern "C" void kernel_launch(void* const* d_in, const int* in_sizes, int n_in,
                              void* d_out, int out_size) {
    const float* x      = (const float*)d_in[0];
    const int*   eidx   = (const int*)  d_in[1];
    const float* proj_w = (const float*)d_in[2];
    const float* W1     = (const float*)d_in[3];
    const float* b1     = (const float*)d_in[4];
    const float* W2     = (const float*)d_in[5];
    const float* b2     = (const float*)d_in[6];
    const float* gw1    = (const float*)d_in[7];
    const float* gb1    = (const float*)d_in[8];
    const float* gw2    = (const float*)d_in[9];
    const float* gb2    = (const float*)d_in[10];
    const float* sw     = (const float*)d_in[11];
    const float* sb     = (const float*)d_in[12];
    float* out = (float*)d_out;

    const int* e_src = eidx;
    const int* e_dst = eidx + EE;

    float *p_h, *p_HAB, *p_t;
    __half *p_Abig, *p_Rbig, *p_WtAB, *p_WtW2, *p_WtG;
    int *p_deg, *p_off, *p_cur, *p_srcs;
    cudaGetSymbolAddress((void**)&p_h,    g_h);
    cudaGetSymbolAddress((void**)&p_HAB,  g_HAB);
    cudaGetSymbolAddress((void**)&p_t,    g_t);
    cudaGetSymbolAddress((void**)&p_Abig, g_Abig);
    cudaGetSymbolAddress((void**)&p_Rbig, g_Rbig);
    cudaGetSymbolAddress((void**)&p_WtAB, g_WtAB);
    cudaGetSymbolAddress((void**)&p_WtW2, g_WtW2);
    cudaGetSymbolAddress((void**)&p_WtG,  g_WtG);
    cudaGetSymbolAddress((void**)&p_deg,  g_deg);
    cudaGetSymbolAddress((void**)&p_off,  g_off);
    cudaGetSymbolAddress((void**)&p_cur,  g_cur);
    cudaGetSymbolAddress((void**)&p_srcs, g_srcs);

    cudaFuncSetAttribute(mma_gemm<0>, cudaFuncAttributeMaxDynamicSharedMemorySize, MM_SMEM);
    cudaFuncSetAttribute(mma_gemm<1>, cudaFuncAttributeMaxDynamicSharedMemorySize, MM_SMEM);
    cudaFuncSetAttribute(mma_gemm<2>, cudaFuncAttributeMaxDynamicSharedMemorySize, MM_SMEM);
    cudaFuncSetAttribute(mma_gemm<3>, cudaFuncAttributeMaxDynamicSharedMemorySize, MM_SMEM);

    const int NBM = (NN + BM - 1) / BM;      // 79
    dim3 gAB(2048 / BN, NBM);                // (16, 79)
    dim3 gW2(HID / BN, NBM);                 // (8, 79)
    dim3 ghead(256 / BN, NBM);               // (2, 79)
    float* h_last = out + NN + (size_t)NN * SD;   // final h lives in d_out directly

    // All weight conversions, one launch
    convW_all<<<dim3(32, 32, 13), dim3(32, 8)>>>(W1, W2, gw1, p_WtAB, p_WtW2, p_WtG);

    // CSR build
    zero_int_kernel<<<(NN + 255) / 256, 256>>>(p_deg, NN);
    hist_kernel<<<(EE + 255) / 256, 256>>>(e_dst, p_deg);
    scan_kernel<<<1, 1024>>>(p_deg, p_off, p_cur);
    scatter_kernel<<<(EE + 255) / 256, 256>>>(e_src, e_dst, p_cur, p_srcs);
    sort_kernel<<<(NN + 255) / 256, 256>>>(p_off, p_srcs);

    // Phase embedding -> Abig (fp16 split)
    proj_kernel<<<(NN * HID + 255) / 256, 256>>>(x, proj_w, p_Abig);

    // Layers: layers 0..2 skip the dead fp32 h store (MODE 3)
    for (int l = 0; l < LAYERS; l++) {
        const __half* WtAB = p_WtAB + (size_t)l * 2048 * K2;
        const __half* WtW2 = p_WtW2 + (size_t)l * HID * K2;
        const float* b1l = b1 + (size_t)l * HID;
        const float* b2l = b2 + (size_t)l * HID;

        mma_gemm<0><<<gAB, 128, MM_SMEM>>>(p_Abig, WtAB, p_HAB, NN, 2048, nullptr, nullptr, nullptr);
        edge_agg_kernel<<<NN, 256>>>(p_HAB, p_off, p_srcs, b1l, p_Rbig);
        if (l == LAYERS - 1)
            mma_gemm<1><<<gW2, 128, MM_SMEM>>>(p_Rbig, WtW2, h_last, NN, HID, b2l, p_deg, p_Abig);
        else
            mma_gemm<3><<<gW2, 128, MM_SMEM>>>(p_Rbig, WtW2, p_h, NN, HID, b2l, p_deg, p_Abig);
    }

    // Heads (final h already resides in d_out)
    mma_gemm<2><<<ghead, 128, MM_SMEM>>>(p_Abig, p_WtG, p_t, NN, 256, gb1, nullptr, nullptr);
    ghost_kernel<<<(NN * 32 + 255) / 256, 256>>>(p_t, gw2, gb2, out);
    stable_kernel<<<NN, dim3(32, SD)>>>(h_last, sw, sb, out + NN);
}

// round 14
// speedup vs baseline: 1.5375x; 1.0121x over previous
#include <cuda_runtime.h>
#include <cuda_fp16.h>
#include <math.h>
#include <stdint.h>

// Problem constants
#define NN   10000
#define EE   80000
#define SD   18
#define HID  1024
#define K2   2048          // fp16 2-term split: A=[hi|lo], W=[whi|whi]
#define LAYERS 4

// GEMM tiling: BM=BN=128, BK=64, 128 threads (4 warps, 2x2 grid of 64x64 warp tiles)
#define BM 128
#define BN 128
#define BK 64
#define STG 3
#define NK (K2 / BK)               // 32
#define TILE_BYTES (128 * 128)     // 16384
#define STAGE_BYTES (2 * TILE_BYTES)
#define MM_SMEM (STG * STAGE_BYTES)   // 98304

// ---------------------------------------------------------------------------
// Scratch (device globals — no runtime allocation allowed)
// ---------------------------------------------------------------------------
__device__ float g_h  [NN * HID];
__device__ float g_HAB[NN * 2048];
__device__ float g_t  [NN * 256];
__device__ __half g_Abig[NN * K2];
__device__ __half g_Rbig[NN * K2];
__device__ __half g_WtAB[LAYERS * 2048 * K2];
__device__ __half g_WtW2[LAYERS * HID * K2];
__device__ __half g_WtG [256 * K2];
__device__ int   g_deg[NN];
__device__ int   g_off[NN + 1];
__device__ int   g_cur[NN];
__device__ int   g_srcs[EE];

// ---------------------------------------------------------------------------
// PTX helpers (baseline ISA only: cp.async / ldmatrix / mma.sync)
// ---------------------------------------------------------------------------
__device__ __forceinline__ uint32_t smem_u32(const void* p) {
    uint32_t a;
    asm("{ .reg .u64 t; cvta.to.shared.u64 t, %1; cvt.u32.u64 %0, t; }" : "=r"(a) : "l"(p));
    return a;
}
__device__ __forceinline__ void cp16(uint32_t dst, const void* src, bool valid) {
    int sz = valid ? 16 : 0;
    asm volatile("cp.async.cg.shared.global [%0], [%1], 16, %2;" :: "r"(dst), "l"(src), "r"(sz) : "memory");
}
__device__ __forceinline__ void cp_commit() { asm volatile("cp.async.commit_group;" ::: "memory"); }
__device__ __forceinline__ void ldm_x4(uint32_t& r0, uint32_t& r1, uint32_t& r2, uint32_t& r3,
                                       uint32_t addr) {
    asm volatile("ldmatrix.sync.aligned.m8n8.x4.shared.b16 {%0,%1,%2,%3}, [%4];"
                 : "=r"(r0), "=r"(r1), "=r"(r2), "=r"(r3) : "r"(addr));
}
__device__ __forceinline__ void mma_fp16(float& c0, float& c1, float& c2, float& c3,
                                         uint32_t a0, uint32_t a1, uint32_t a2, uint32_t a3,
                                         uint32_t b0, uint32_t b1) {
    asm volatile(
        "mma.sync.aligned.m16n8k16.row.col.f32.f16.f16.f32 "
        "{%0,%1,%2,%3}, {%4,%5,%6,%7}, {%8,%9}, {%0,%1,%2,%3};"
        : "+f"(c0), "+f"(c1), "+f"(c2), "+f"(c3)
        : "r"(a0), "r"(a1), "r"(a2), "r"(a3), "r"(b0), "r"(b1));
}

// ---------------------------------------------------------------------------
// HMMA GEMM: C[M, Nstride] = A[M, K2] @ Bt[N, K2]^T  (fp16 in, fp32 out)
// MODE 0: plain C
// MODE 1: v = relu(acc + deg[row]*bias[col]); writes C (fp32) AND abig split
// MODE 2: relu(acc + bias[col]) -> C
// MODE 3: v = relu(acc + deg[row]*bias[col]); writes abig split ONLY
// 128 threads, 4 warps in 2(M) x 2(N); warp tile 64x64; frag m16n8k16.
// Single-buffer fragments (R10 layout): at 2 CTAs/SM the warp mix already
// hides LDSM latency; extra fragment buffers spill and regress (R11 lesson).
// ---------------------------------------------------------------------------
template <int MODE>
__global__ void __launch_bounds__(128, 2)
mma_gemm(const __half* __restrict__ A, const __half* __restrict__ Bt,
         float* __restrict__ C, int M, int Nstride,
         const float* __restrict__ bias, const int* __restrict__ deg,
         __half* __restrict__ abig) {
    extern __shared__ char smem[];
    const uint32_t sb = smem_u32(smem);
    const int tid  = threadIdx.x;
    const int wid  = tid >> 5;
    const int lane = tid & 31;
    const int bm   = blockIdx.y * BM;
    const int bn   = blockIdx.x * BN;
    const int warp_m = (wid & 1) * 64;
    const int warp_n = (wid >> 1) * 64;

    const char* gA = (const char*)A  + (size_t)bm * (K2 * 2);
    const char* gB = (const char*)Bt + (size_t)bn * (K2 * 2);
    const int lrow = tid >> 3;
    const int qq   = (tid & 7) * 16;

    auto load_chunk = [&](int kc, int s) {
        uint32_t sa = sb + s * STAGE_BYTES;
        uint32_t sB = sa + TILE_BYTES;
        size_t kb = (size_t)kc * (BK * 2);
#pragma unroll
        for (int u = 0; u < 8; u++) {
            int row = lrow + u * 16;
            uint32_t sw = row * 128 + (qq ^ ((row & 7) << 4));
            cp16(sa + sw, gA + (size_t)row * (K2 * 2) + kb + qq, (bm + row) < M);
            cp16(sB + sw, gB + (size_t)row * (K2 * 2) + kb + qq, true);
        }
        cp_commit();
    };

    // ldmatrix lane patterns
    const int g  = lane >> 3;
    const int lr = lane & 7;
    const int swz = lr << 4;
    const int A_row = (g & 1) * 8 + lr;
    const int A_col = (g >> 1) * 16;
    const int B_row = (g >> 1) * 8 + lr;
    const int B_col = (g & 1) * 16;

    float acc[4][8][4];
#pragma unroll
    for (int i = 0; i < 4; i++)
#pragma unroll
        for (int j = 0; j < 8; j++)
#pragma unroll
            for (int q = 0; q < 4; q++) acc[i][j][q] = 0.f;

    // prologue
#pragma unroll
    for (int s = 0; s < STG - 1; s++) load_chunk(s, s);

    for (int it = 0; it < NK; it++) {
        asm volatile("cp.async.wait_group %0;" :: "n"(STG - 2) : "memory");
        __syncthreads();
        int cl = it + STG - 1;
        if (cl < NK) load_chunk(cl, cl % STG);
        else         cp_commit();      // empty group keeps wait_group bookkeeping valid

        uint32_t sa = sb + (it % STG) * STAGE_BYTES;
        uint32_t sB = sa + TILE_BYTES;
        uint32_t aBase = sa + (warp_m + A_row) * 128;
        uint32_t bBase = sB + (warp_n + B_row) * 128;
#pragma unroll
        for (int kk = 0; kk < 4; kk++) {
            uint32_t a[4][4], b[4][4];
            uint32_t aoff = (uint32_t)((kk * 32 + A_col) ^ swz);
            uint32_t boff = (uint32_t)((kk * 32 + B_col) ^ swz);
#pragma unroll
            for (int mt = 0; mt < 4; mt++)
                ldm_x4(a[mt][0], a[mt][1], a[mt][2], a[mt][3],
                       aBase + mt * (16 * 128) + aoff);
#pragma unroll
            for (int nt2 = 0; nt2 < 4; nt2++)
                ldm_x4(b[nt2][0], b[nt2][1], b[nt2][2], b[nt2][3],
                       bBase + nt2 * (16 * 128) + boff);
#pragma unroll
            for (int mt = 0; mt < 4; mt++)
#pragma unroll
                for (int nt = 0; nt < 8; nt++) {
                    uint32_t bb0 = b[nt >> 1][(nt & 1) * 2 + 0];
                    uint32_t bb1 = b[nt >> 1][(nt & 1) * 2 + 1];
                    mma_fp16(acc[mt][nt][0], acc[mt][nt][1], acc[mt][nt][2], acc[mt][nt][3],
                             a[mt][0], a[mt][1], a[mt][2], a[mt][3], bb0, bb1);
                }
        }
    }

    // epilogue (register-only inputs; no smem reads, no barrier needed)
    const int tq = lane >> 2;      // 0..7
    const int tr = lane & 3;       // 0..3
#pragma unroll
    for (int mt = 0; mt < 4; mt++) {
#pragma unroll
        for (int half = 0; half < 2; half++) {
            int row = bm + warp_m + mt * 16 + half * 8 + tq;
            if (row >= M) continue;
            float degf = 0.f;
            if (MODE == 1 || MODE == 3) degf = (float)deg[row];
#pragma unroll
            for (int nt = 0; nt < 8; nt++) {
                int col = bn + warp_n + nt * 8 + tr * 2;
                float vx = acc[mt][nt][half * 2 + 0];
                float vy = acc[mt][nt][half * 2 + 1];
                if (MODE == 1 || MODE == 3) {
                    vx = fmaxf(fmaf(degf, bias[col + 0], vx), 0.f);
                    vy = fmaxf(fmaf(degf, bias[col + 1], vy), 0.f);
                } else if (MODE == 2) {
                    vx = fmaxf(vx + bias[col + 0], 0.f);
                    vy = fmaxf(vy + bias[col + 1], 0.f);
                }
                if (MODE != 3)
                    *reinterpret_cast<float2*>(&C[(size_t)row * Nstride + col]) = make_float2(vx, vy);
                if (MODE == 1 || MODE == 3) {
                    __half hx = __float2half(vx);
                    __half hy = __float2half(vy);
                    __half lx = __float2half(vx - __half2float(hx));
                    __half ly = __float2half(vy - __half2float(hy));
                    size_t base = (size_t)row * K2 + col;
                    *reinterpret_cast<__half2*>(&abig[base])       = __halves2half2(hx, hy);
                    *reinterpret_cast<__half2*>(&abig[base + HID]) = __halves2half2(lx, ly);
                }
            }
        }
    }
}

// ---------------------------------------------------------------------------
// All weight conversions in ONE launch. blockIdx.z selects the slice.
// ---------------------------------------------------------------------------
__global__ void convW_all(const float* __restrict__ W1, const float* __restrict__ W2,
                          const float* __restrict__ gw1,
                          __half* __restrict__ WtAB, __half* __restrict__ WtW2,
                          __half* __restrict__ WtG) {
    const size_t KK = (size_t)HID * HID;
    int s = blockIdx.z;
    const float* Wa;
    const float* Wb = nullptr;
    __half* out;
    int N = HID;
    if (s < 12) {
        int l = s / 3, k = s - l * 3;
        if (k == 0)      { Wa = W1 + (size_t)l * 2 * KK; Wb = Wa + KK; out = WtAB + (size_t)l * 2048 * K2; }
        else if (k == 1) { Wa = W1 + (size_t)l * 2 * KK + KK;          out = WtAB + (size_t)l * 2048 * K2 + (size_t)1024 * K2; }
        else             { Wa = W2 + (size_t)l * KK;                   out = WtW2 + (size_t)l * HID * K2; }
    } else { Wa = gw1; out = WtG; N = 256; }

    int n0 = blockIdx.x * 32, k0 = blockIdx.y * 32;
    if (n0 >= N) return;
    __shared__ float t[32][33];
    int tx = threadIdx.x, ty = threadIdx.y;
#pragma unroll
    for (int r = ty; r < 32; r += 8) {
        float v = Wa[(size_t)(k0 + r) * N + n0 + tx];
        if (Wb) v -= Wb[(size_t)(k0 + r) * N + n0 + tx];
        t[r][tx] = v;
    }
    __syncthreads();
#pragma unroll
    for (int r = ty; r < 32; r += 8) {
        int n = n0 + r, k = k0 + tx;
        __half hi = __float2half(t[tx][r]);
        size_t base = (size_t)n * K2;
        out[base + k] = hi;
        out[base + HID + k] = hi;
    }
}

// ---------------------------------------------------------------------------
// CSR build (deterministic)
// ---------------------------------------------------------------------------
__global__ void zero_int_kernel(int* p, int n) {
    int i = blockIdx.x * blockDim.x + threadIdx.x;
    if (i < n) p[i] = 0;
}
__global__ void hist_kernel(const int* __restrict__ dst, int* __restrict__ deg) {
    int e = blockIdx.x * blockDim.x + threadIdx.x;
    if (e < EE) atomicAdd(&deg[dst[e]], 1);
}
// single-block scan: 10 nodes/thread; warp shfl scans, 2 barriers; seeds cur[]
__global__ void scan_kernel(const int* __restrict__ deg, int* __restrict__ off,
                            int* __restrict__ cur) {
    __shared__ int wsum[32];
    int t = threadIdx.x;
    int lane = t & 31, warp = t >> 5;
    int base = t * 10;
    int v[10];
    int s = 0;
#pragma unroll
    for (int u = 0; u < 10; u++) {
        int i = base + u;
        v[u] = (i < NN) ? deg[i] : 0;
        s += v[u];
    }
    // warp-inclusive scan of per-thread sums
    int x = s;
#pragma unroll
    for (int d = 1; d < 32; d <<= 1) {
        int y = __shfl_up_sync(0xFFFFFFFFu, x, d);
        if (lane >= d) x += y;
    }
    if (lane == 31) wsum[warp] = x;
    __syncthreads();
    if (warp == 0) {
        int w = wsum[lane];
#pragma unroll
        for (int d = 1; d < 32; d <<= 1) {
            int y = __shfl_up_sync(0xFFFFFFFFu, w, d);
            if (lane >= d) w += y;
        }
        wsum[lane] = w;
    }
    __syncthreads();
    int run = x - s + (warp ? wsum[warp - 1] : 0);   // exclusive prefix for this thread
#pragma unroll
    for (int u = 0; u < 10; u++) {
        int i = base + u;
        if (i < NN) cur[i] = run;
        run += v[u];
        if (i < NN) off[i + 1] = run;
    }
    if (t == 0) off[0] = 0;
}
__global__ void scatter_kernel(const int* __restrict__ src, const int* __restrict__ dst,
                               int* __restrict__ cur, int* __restrict__ srcs) {
    int e = blockIdx.x * blockDim.x + threadIdx.x;
    if (e < EE) {
        int p = atomicAdd(&cur[dst[e]], 1);
        srcs[p] = src[e];
    }
}
__global__ void sort_kernel(const int* __restrict__ off, int* __restrict__ srcs) {
    int i = blockIdx.x * blockDim.x + threadIdx.x;
    if (i >= NN) return;
    int a = off[i], b = off[i + 1];
    for (int x = a + 1; x < b; x++) {
        int v = srcs[x];
        int y = x - 1;
        while (y >= a && srcs[y] > v) { srcs[y + 1] = srcs[y]; y--; }
        srcs[y + 1] = v;
    }
}

// ---------------------------------------------------------------------------
// Phase embedding: writes fp16 split Abig directly
// ---------------------------------------------------------------------------
__global__ void proj_kernel(const float* __restrict__ x, const float* __restrict__ pw,
                            __half* __restrict__ Abig) {
    int idx = blockIdx.x * blockDim.x + threadIdx.x;
    if (idx >= NN * HID) return;
    int n = idx >> 10, j = idx & (HID - 1);
    float p = 0.f;
#pragma unroll
    for (int k = 0; k < SD; k++) p = fmaf(x[n * SD + k], pw[k * HID + j], p);
    float v = sinf(p) * cosf(p);
    __half hi = __float2half(v);
    __half lo = __float2half(v - __half2float(hi));
    size_t base = (size_t)n * K2;
    Abig[base + j] = hi;
    Abig[base + HID + j] = lo;
}

// ---------------------------------------------------------------------------
// Edge aggregation: R[i] = sum relu(HA[i] + HB[src] + b1); writes fp16 split
// ---------------------------------------------------------------------------
__global__ void edge_agg_kernel(const float* __restrict__ HAB,
                                const int* __restrict__ off, const int* __restrict__ srcs,
                                const float* __restrict__ b1, __half* __restrict__ Rbig) {
    int i   = blockIdx.x;
    int tid = threadIdx.x;
    float ha[4], acc[4];
#pragma unroll
    for (int u = 0; u < 4; u++) {
        int j  = tid + u * 256;
        ha[u]  = HAB[(size_t)i * 2048 + j] + b1[j];
        acc[u] = 0.f;
    }
    int s0 = off[i], s1 = off[i + 1];
    for (int e = s0; e < s1; e++) {
        int s = srcs[e];
        const float* hb = HAB + (size_t)s * 2048 + 1024;
#pragma unroll
        for (int u = 0; u < 4; u++) acc[u] += fmaxf(ha[u] + hb[tid + u * 256], 0.f);
    }
    size_t base = (size_t)i * K2;
#pragma unroll
    for (int u = 0; u < 4; u++) {
        int j = tid + u * 256;
        float v = acc[u];
        __half hi = __float2half(v);
        __half lo = __float2half(v - __half2float(hi));
        Rbig[base + j] = hi;
        Rbig[base + HID + j] = lo;
    }
}

// ---------------------------------------------------------------------------
// Heads
// ---------------------------------------------------------------------------
__global__ void ghost_kernel(const float* __restrict__ t, const float* __restrict__ gw2,
                             const float* __restrict__ gb2, float* __restrict__ out) {
    int warp = (blockIdx.x * blockDim.x + threadIdx.x) >> 5;
    int lane = threadIdx.x & 31;
    if (warp >= NN) return;
    float s = 0.f;
#pragma unroll
    for (int k = lane; k < 256; k += 32) s = fmaf(t[(size_t)warp * 256 + k], gw2[k], s);
#pragma unroll
    for (int o = 16; o; o >>= 1) s += __shfl_xor_sync(0xFFFFFFFFu, s, o);
    if (lane == 0) out[warp] = 1.f / (1.f + expf(-(s + gb2[0])));
}
__global__ void stable_kernel(const float* __restrict__ h, const float* __restrict__ sw,
                              const float* __restrict__ sb, float* __restrict__ out) {
    int n    = blockIdx.x;
    int c    = threadIdx.y;
    int lane = threadIdx.x;
    float s  = 0.f;
    for (int k = lane; k < HID; k += 32) s = fmaf(h[(size_t)n * HID + k], sw[k * SD + c], s);
#pragma unroll
    for (int o = 16; o; o >>= 1) s += __shfl_xor_sync(0xFFFFFFFFu, s, o);
    if (lane == 0) out[(size_t)n * SD + c] = s + sb[c];
}

// ---------------------------------------------------------------------------
// Launch — prologue and tail use a forked auxiliary stream (capture-legal
// event fork/join). Streams/events created once on the first (uncaptured)
// correctness call; no device memory involved.
// ---------------------------------------------------------------------------
extern "C" void kernel_launch(void* const* d_in, const int* in_sizes, int n_in,
                              void* d_out, int out_size) {
    const float* x      = (const float*)d_in[0];
    const int*   eidx   = (const int*)  d_in[1];
    const float* proj_w = (const float*)d_in[2];
    const float* W1     = (const float*)d_in[3];
    const float* b1     = (const float*)d_in[4];
    const float* W2     = (const float*)d_in[5];
    const float* b2     = (const float*)d_in[6];
    const float* gw1    = (const float*)d_in[7];
    const float* gb1    = (const float*)d_in[8];
    const float* gw2    = (const float*)d_in[9];
    const float* gb2    = (const float*)d_in[10];
    const float* sw     = (const float*)d_in[11];
    const float* sb     = (const float*)d_in[12];
    float* out = (float*)d_out;

    const int* e_src = eidx;
    const int* e_dst = eidx + EE;

    float *p_h, *p_HAB, *p_t;
    __half *p_Abig, *p_Rbig, *p_WtAB, *p_WtW2, *p_WtG;
    int *p_deg, *p_off, *p_cur, *p_srcs;
    cudaGetSymbolAddress((void**)&p_h,    g_h);
    cudaGetSymbolAddress((void**)&p_HAB,  g_HAB);
    cudaGetSymbolAddress((void**)&p_t,    g_t);
    cudaGetSymbolAddress((void**)&p_Abig, g_Abig);
    cudaGetSymbolAddress((void**)&p_Rbig, g_Rbig);
    cudaGetSymbolAddress((void**)&p_WtAB, g_WtAB);
    cudaGetSymbolAddress((void**)&p_WtW2, g_WtW2);
    cudaGetSymbolAddress((void**)&p_WtG,  g_WtG);
    cudaGetSymbolAddress((void**)&p_deg,  g_deg);
    cudaGetSymbolAddress((void**)&p_off,  g_off);
    cudaGetSymbolAddress((void**)&p_cur,  g_cur);
    cudaGetSymbolAddress((void**)&p_srcs, g_srcs);

    cudaFuncSetAttribute(mma_gemm<0>, cudaFuncAttributeMaxDynamicSharedMemorySize, MM_SMEM);
    cudaFuncSetAttribute(mma_gemm<1>, cudaFuncAttributeMaxDynamicSharedMemorySize, MM_SMEM);
    cudaFuncSetAttribute(mma_gemm<2>, cudaFuncAttributeMaxDynamicSharedMemorySize, MM_SMEM);
    cudaFuncSetAttribute(mma_gemm<3>, cudaFuncAttributeMaxDynamicSharedMemorySize, MM_SMEM);

    static cudaStream_t s_aux = nullptr;
    static cudaEvent_t ev_fork = nullptr, ev_join = nullptr, ev_w2 = nullptr, ev_tail = nullptr;
    if (s_aux == nullptr) {
        cudaStreamCreateWithFlags(&s_aux, cudaStreamNonBlocking);
        cudaEventCreateWithFlags(&ev_fork, cudaEventDisableTiming);
        cudaEventCreateWithFlags(&ev_join, cudaEventDisableTiming);
        cudaEventCreateWithFlags(&ev_w2,   cudaEventDisableTiming);
        cudaEventCreateWithFlags(&ev_tail, cudaEventDisableTiming);
    }

    const int NBM = (NN + BM - 1) / BM;      // 79
    dim3 gAB(2048 / BN, NBM);                // (16, 79)
    dim3 gW2(HID / BN, NBM);                 // (8, 79)
    dim3 ghead(256 / BN, NBM);               // (2, 79)
    float* h_last = out + NN + (size_t)NN * SD;   // final h lives in d_out directly

    // --- prologue fork: aux does weight conversion + embedding, main does CSR ---
    cudaEventRecord(ev_fork, 0);
    cudaStreamWaitEvent(s_aux, ev_fork, 0);

    convW_all<<<dim3(32, 32, 13), dim3(32, 8), 0, s_aux>>>(W1, W2, gw1, p_WtAB, p_WtW2, p_WtG);
    proj_kernel<<<(NN * HID + 255) / 256, 256, 0, s_aux>>>(x, proj_w, p_Abig);

    zero_int_kernel<<<(NN + 255) / 256, 256>>>(p_deg, NN);
    hist_kernel<<<(EE + 255) / 256, 256>>>(e_dst, p_deg);
    scan_kernel<<<1, 1024>>>(p_deg, p_off, p_cur);
    scatter_kernel<<<(EE + 255) / 256, 256>>>(e_src, e_dst, p_cur, p_srcs);
    sort_kernel<<<(NN + 255) / 256, 256>>>(p_off, p_srcs);

    cudaEventRecord(ev_join, s_aux);
    cudaStreamWaitEvent(0, ev_join, 0);

    // --- layers (main stream): layers 0..2 skip the dead fp32 h store (MODE 3) ---
    for (int l = 0; l < LAYERS; l++) {
        const __half* WtAB = p_WtAB + (size_t)l * 2048 * K2;
        const __half* WtW2 = p_WtW2 + (size_t)l * HID * K2;
        const float* b1l = b1 + (size_t)l * HID;
        const float* b2l = b2 + (size_t)l * HID;

        mma_gemm<0><<<gAB, 128, MM_SMEM>>>(p_Abig, WtAB, p_HAB, NN, 2048, nullptr, nullptr, nullptr);
        edge_agg_kernel<<<NN, 256>>>(p_HAB, p_off, p_srcs, b1l, p_Rbig);
        if (l == LAYERS - 1)
            mma_gemm<1><<<gW2, 128, MM_SMEM>>>(p_Rbig, WtW2, h_last, NN, HID, b2l, p_deg, p_Abig);
        else
            mma_gemm<3><<<gW2, 128, MM_SMEM>>>(p_Rbig, WtW2, p_h, NN, HID, b2l, p_deg, p_Abig);
    }

    // --- tail fork: stable head (depends only on h_last) runs on aux,
    //     concurrent with head GEMM + ghost on the main stream ---
    cudaEventRecord(ev_w2, 0);
    cudaStreamWaitEvent(s_aux, ev_w2, 0);
    stable_kernel<<<NN, dim3(32, SD), 0, s_aux>>>(h_last, sw, sb, out + NN);
    cudaEventRecord(ev_tail, s_aux);

    mma_gemm<2><<<ghead, 128, MM_SMEM>>>(p_Abig, p_WtG, p_t, NN, 256, gb1, nullptr, nullptr);
    ghost_kernel<<<(NN * 32 + 255) / 256, 256>>>(p_t, gw2, gb2, out);

    cudaStreamWaitEvent(0, ev_tail, 0);
}